// round 2
// baseline (speedup 1.0000x reference)
#include <cuda_runtime.h>
#include <cuda_bf16.h>

#define NN 50000
#define NE 800000
#define INC 128
#define HID 96
#define OUTC 40

__device__ float g_deg[NN];
__device__ float g_dinv[NN];
__device__ float g_selfw[NN];
__device__ float g_w[NE];
__device__ float g_h0[NN * HID];
__device__ float g_t [NN * HID];
__device__ float g_acc[NN * HID];
__device__ float g_u [NN * HID];
__device__ float g_b [NN * HID];
__device__ float g_c [NN * OUTC];
__device__ float g_sum[3 * HID];
__device__ float g_sq [3 * HID];
__device__ float g_mean[HID];
__device__ float g_scl[HID];

// ---------------------------------------------------------------------------
// Prep kernels
// ---------------------------------------------------------------------------
__global__ void zero_prep_kernel() {
    int i = blockIdx.x * blockDim.x + threadIdx.x;
    if (i < NN) g_deg[i] = 0.f;
    if (i < 3 * HID) { g_sum[i] = 0.f; g_sq[i] = 0.f; }
}

__global__ void deg_kernel(const int* __restrict__ ei) {
    int e = blockIdx.x * blockDim.x + threadIdx.x;
    if (e >= NE) return;
    int s = ei[e];
    int d = ei[NE + e];
    if (s != d) atomicAdd(&g_deg[d], 1.f);
}

__global__ void fin_deg_kernel() {
    int i = blockIdx.x * blockDim.x + threadIdx.x;
    if (i >= NN) return;
    float d = g_deg[i] + 1.f;
    g_dinv[i]  = rsqrtf(d);
    g_selfw[i] = 1.f / d;
}

__global__ void edgew_kernel(const int* __restrict__ ei) {
    int e = blockIdx.x * blockDim.x + threadIdx.x;
    if (e >= NE) return;
    int s = ei[e];
    int d = ei[NE + e];
    g_w[e] = (s != d) ? g_dinv[s] * g_dinv[d] : 0.f;
}

// ---------------------------------------------------------------------------
// Register-tiled SGEMM: Out[N, NOUT] = A[N, K] @ W[NOUT, K]^T
// Optional GCNII blend epilogue: Out = beta*acc + (1-beta)*blendSrc
// ---------------------------------------------------------------------------
template <int K, int NOUT, int TM, int TN, int TX, int TY>
__global__ void gemm_kernel(const float* __restrict__ A,
                            const float* __restrict__ Wg,
                            float* __restrict__ Out,
                            const float* __restrict__ blendSrc,
                            float beta) {
    constexpr int BM = TM * TY;
    constexpr int NT = TX * TY;
    __shared__ float xs[BM][17];
    __shared__ float ws[16][NOUT];

    int tid = threadIdx.x;
    int tx = tid % TX;
    int ty = tid / TX;
    int rowbase = blockIdx.x * BM;

    float acc[TM][TN];
#pragma unroll
    for (int r = 0; r < TM; r++)
#pragma unroll
        for (int c = 0; c < TN; c++) acc[r][c] = 0.f;

    for (int k0 = 0; k0 < K; k0 += 16) {
        __syncthreads();
        for (int i = tid; i < BM * 16; i += NT) {
            int r = i >> 4, c = i & 15;
            int row = rowbase + r;
            xs[r][c] = (row < NN) ? A[(size_t)row * K + k0 + c] : 0.f;
        }
        for (int i = tid; i < 16 * NOUT; i += NT) {
            int kk = i & 15, n = i >> 4;
            ws[kk][n] = Wg[(size_t)n * K + k0 + kk];
        }
        __syncthreads();
#pragma unroll
        for (int kk = 0; kk < 16; kk++) {
            float a[TM], b[TN];
#pragma unroll
            for (int r = 0; r < TM; r++) a[r] = xs[ty * TM + r][kk];
#pragma unroll
            for (int c = 0; c < TN; c++) b[c] = ws[kk][tx * TN + c];
#pragma unroll
            for (int r = 0; r < TM; r++)
#pragma unroll
                for (int c = 0; c < TN; c++) acc[r][c] += a[r] * b[c];
        }
    }

#pragma unroll
    for (int r = 0; r < TM; r++) {
        int row = rowbase + ty * TM + r;
        if (row >= NN) continue;
#pragma unroll
        for (int c = 0; c < TN; c++) {
            int col = tx * TN + c;
            float v = acc[r][c];
            if (beta != 1.f)
                v = beta * v + (1.f - beta) * blendSrc[(size_t)row * NOUT + col];
            Out[(size_t)row * NOUT + col] = v;
        }
    }
}

// ---------------------------------------------------------------------------
// BatchNorm stats, finalize, apply+ReLU
// ---------------------------------------------------------------------------
__global__ void stats_kernel(const float* __restrict__ X,
                             float* __restrict__ sums, float* __restrict__ sq) {
    __shared__ float ss[4][HID];
    __shared__ float qq[4][HID];
    int c = threadIdx.x;
    int ty = threadIdx.y;
    float s = 0.f, q = 0.f;
    for (int r = blockIdx.x * 4 + ty; r < NN; r += gridDim.x * 4) {
        float v = X[(size_t)r * HID + c];
        s += v;
        q += v * v;
    }
    ss[ty][c] = s;
    qq[ty][c] = q;
    __syncthreads();
    if (ty == 0) {
        s = ss[0][c] + ss[1][c] + ss[2][c] + ss[3][c];
        q = qq[0][c] + qq[1][c] + qq[2][c] + qq[3][c];
        atomicAdd(&sums[c], s);
        atomicAdd(&sq[c], q);
    }
}

__global__ void bn_final_kernel(const float* __restrict__ sums,
                                const float* __restrict__ sq) {
    int c = threadIdx.x;
    if (c < HID) {
        const float invN = 1.f / (float)NN;
        float m = sums[c] * invN;
        float v = sq[c] * invN - m * m;
        g_mean[c] = m;
        g_scl[c] = rsqrtf(v + 1e-5f);
    }
}

__global__ void bnrelu_kernel(const float* __restrict__ X, float* __restrict__ Y) {
    int idx = blockIdx.x * blockDim.x + threadIdx.x;
    if (idx >= NN * HID) return;
    int c = idx % HID;
    float v = (X[idx] - g_mean[c]) * g_scl[c];
    Y[idx] = fmaxf(v, 0.f);
}

// ---------------------------------------------------------------------------
// SpMM scatter + combine epilogues
// ---------------------------------------------------------------------------
__global__ void zero_acc_kernel() {
    int idx = blockIdx.x * blockDim.x + threadIdx.x;
    if (idx < NN * HID) g_acc[idx] = 0.f;
}

__global__ void zero_out_kernel(float* __restrict__ p, int n) {
    int idx = blockIdx.x * blockDim.x + threadIdx.x;
    if (idx < n) p[idx] = 0.f;
}

template <int F>
__global__ void scatter_kernel(const int* __restrict__ ei,
                               const float* __restrict__ X,
                               float* __restrict__ acc) {
    int e = blockIdx.x * blockDim.x + threadIdx.x;
    if (e >= NE) return;
    float wt = g_w[e];
    if (wt == 0.f) return;
    const float4* src = (const float4*)(X + (size_t)ei[e] * F);
    float4* dst = (float4*)(acc + (size_t)ei[NE + e] * F);
#pragma unroll
    for (int j = 0; j < F / 4; j++) {
        float4 v = __ldg(&src[j]);
        atomicAdd(&dst[j], make_float4(wt * v.x, wt * v.y, wt * v.z, wt * v.w));
    }
}

// u = 0.9*(acc + selfw*t) + 0.1*h0
__global__ void combine_kernel(const float* __restrict__ acc,
                               const float* __restrict__ t,
                               float* __restrict__ u) {
    int idx = blockIdx.x * blockDim.x + threadIdx.x;
    if (idx >= NN * HID) return;
    int row = idx / HID;
    u[idx] = 0.9f * (acc[idx] + g_selfw[row] * t[idx]) + 0.1f * g_h0[idx];
}

// out += selfw * C
__global__ void selfadd_kernel(const float* __restrict__ C, float* __restrict__ out) {
    int idx = blockIdx.x * blockDim.x + threadIdx.x;
    if (idx >= NN * OUTC) return;
    int row = idx / OUTC;
    out[idx] += g_selfw[row] * C[idx];
}

// ---------------------------------------------------------------------------
extern "C" void kernel_launch(void* const* d_in, const int* in_sizes, int n_in,
                              void* d_out, int out_size) {
    const float* x  = (const float*)d_in[0];
    const int*   ei = (const int*)d_in[1];
    const float* W0 = (const float*)d_in[2];
    const float* W1 = (const float*)d_in[3];
    const float* W2 = (const float*)d_in[4];
    const float* W3 = (const float*)d_in[5];
    float* out = (float*)d_out;

    float *ph0, *pt, *pacc, *pu, *pb, *pc, *psum, *psq;
    cudaGetSymbolAddress((void**)&ph0, g_h0);
    cudaGetSymbolAddress((void**)&pt, g_t);
    cudaGetSymbolAddress((void**)&pacc, g_acc);
    cudaGetSymbolAddress((void**)&pu, g_u);
    cudaGetSymbolAddress((void**)&pb, g_b);
    cudaGetSymbolAddress((void**)&pc, g_c);
    cudaGetSymbolAddress((void**)&psum, g_sum);
    cudaGetSymbolAddress((void**)&psq, g_sq);

    const int gbE = (NE + 255) / 256;
    const int gbN = (NN + 255) / 256;
    const int gbH = (NN * HID + 255) / 256;
    const int gbO = (NN * OUTC + 255) / 256;
    const int gbG = (NN + 127) / 128;
    dim3 statsBlk(HID, 4);

    // ---- graph prep ----
    zero_prep_kernel<<<gbN, 256>>>();
    deg_kernel<<<gbE, 256>>>(ei);
    fin_deg_kernel<<<gbN, 256>>>();
    edgew_kernel<<<gbE, 256>>>(ei);

    // ---- layer 0: h0 = relu(bn(x @ W0^T)) ----
    gemm_kernel<INC, HID, 8, 6, 16, 16><<<gbG, 256>>>(x, W0, pt, nullptr, 1.f);
    stats_kernel<<<128, statsBlk>>>(pt, psum + 0 * HID, psq + 0 * HID);
    bn_final_kernel<<<1, HID>>>(psum + 0 * HID, psq + 0 * HID);
    bnrelu_kernel<<<gbH, 256>>>(pt, ph0);

    // ---- layer 1 (beta = 0.5) ----
    gemm_kernel<HID, HID, 8, 6, 16, 16><<<gbG, 256>>>(ph0, W1, pt, ph0, 0.5f);
    zero_acc_kernel<<<gbH, 256>>>();
    scatter_kernel<HID><<<gbE, 256>>>(ei, pt, pacc);
    combine_kernel<<<gbH, 256>>>(pacc, pt, pu);
    stats_kernel<<<128, statsBlk>>>(pu, psum + 1 * HID, psq + 1 * HID);
    bn_final_kernel<<<1, HID>>>(psum + 1 * HID, psq + 1 * HID);
    bnrelu_kernel<<<gbH, 256>>>(pu, pb);

    // ---- layer 2 (beta = 0.25) ----
    gemm_kernel<HID, HID, 8, 6, 16, 16><<<gbG, 256>>>(pb, W2, pt, pb, 0.25f);
    zero_acc_kernel<<<gbH, 256>>>();
    scatter_kernel<HID><<<gbE, 256>>>(ei, pt, pacc);
    combine_kernel<<<gbH, 256>>>(pacc, pt, pu);
    stats_kernel<<<128, statsBlk>>>(pu, psum + 2 * HID, psq + 2 * HID);
    bn_final_kernel<<<1, HID>>>(psum + 2 * HID, psq + 2 * HID);
    bnrelu_kernel<<<gbH, 256>>>(pu, pb);

    // ---- final: out = spmm(b @ W3^T) ----
    gemm_kernel<HID, OUTC, 4, 5, 8, 32><<<gbG, 256>>>(pb, W3, pc, nullptr, 1.f);
    zero_out_kernel<<<gbO, 256>>>(out, NN * OUTC);
    scatter_kernel<OUTC><<<gbE, 256>>>(ei, pc, out);
    selfadd_kernel<<<gbO, 256>>>(pc, out);
}

// round 3
// speedup vs baseline: 1.7168x; 1.7168x over previous
#include <cuda_runtime.h>
#include <cuda_bf16.h>

#define NN 50000
#define NE 800000
#define INC 128
#define HID 96
#define OUTC 40
#define SCB 196   // scan blocks: 196*256 = 50176 >= NN

__device__ float g_dinv[NN];
__device__ float g_selfw[NN];
__device__ int   g_cnt[NN];
__device__ int   g_fill[NN];
__device__ int   g_rowptr[NN + 1];
__device__ int   g_bsum[256];
__device__ int   g_boff[256];
__device__ int   g_col[NE];
__device__ float g_ew[NE];
__device__ float g_h0[NN * HID];
__device__ float g_t [NN * HID];
__device__ float g_u [NN * HID];
__device__ float g_b [NN * HID];
__device__ float g_c [NN * OUTC];
__device__ float g_sum[3 * HID];
__device__ float g_sq [3 * HID];
__device__ float g_mean[HID];
__device__ float g_scl[HID];

// ---------------------------------------------------------------------------
// f32x2 packed math helpers (Blackwell: ptxas never auto-fuses; explicit PTX)
// ---------------------------------------------------------------------------
__device__ __forceinline__ void ffma2(unsigned long long& acc,
                                      unsigned long long a2,
                                      unsigned long long b2) {
    asm("fma.rn.f32x2 %0, %1, %2, %3;" : "=l"(acc) : "l"(a2), "l"(b2), "l"(acc));
}
__device__ __forceinline__ unsigned long long packrep(float x) {
    unsigned long long r;
    asm("mov.b64 %0, {%1, %1};" : "=l"(r) : "f"(x));
    return r;
}
__device__ __forceinline__ float2 unpack2(unsigned long long v) {
    float2 r;
    asm("mov.b64 {%0, %1}, %2;" : "=f"(r.x), "=f"(r.y) : "l"(v));
    return r;
}

// ---------------------------------------------------------------------------
// Prep: zero counters, count in-degrees, finalize norm weights
// ---------------------------------------------------------------------------
__global__ void zero_prep_kernel() {
    int i = blockIdx.x * blockDim.x + threadIdx.x;
    if (i < NN) { g_cnt[i] = 0; g_fill[i] = 0; }
    if (i < 3 * HID) { g_sum[i] = 0.f; g_sq[i] = 0.f; }
}

__global__ void cnt_kernel(const int* __restrict__ ei) {
    int e = blockIdx.x * blockDim.x + threadIdx.x;
    if (e >= NE) return;
    int s = ei[e];
    int d = ei[NE + e];
    if (s != d) atomicAdd(&g_cnt[d], 1);
}

__global__ void fin_deg_kernel() {
    int i = blockIdx.x * blockDim.x + threadIdx.x;
    if (i >= NN) return;
    float d = (float)g_cnt[i] + 1.f;
    g_dinv[i]  = rsqrtf(d);
    g_selfw[i] = 1.f / d;
}

// ---------------------------------------------------------------------------
// 3-kernel exclusive scan of g_cnt -> g_rowptr
// ---------------------------------------------------------------------------
__global__ void scan1_kernel() {
    __shared__ int sh[256];
    int i = blockIdx.x * 256 + threadIdx.x;
    sh[threadIdx.x] = (i < NN) ? g_cnt[i] : 0;
    __syncthreads();
    for (int o = 128; o > 0; o >>= 1) {
        if (threadIdx.x < o) sh[threadIdx.x] += sh[threadIdx.x + o];
        __syncthreads();
    }
    if (threadIdx.x == 0) g_bsum[blockIdx.x] = sh[0];
}

__global__ void scan2_kernel() {
    __shared__ int sh[256];
    int t = threadIdx.x;
    int v = (t < SCB) ? g_bsum[t] : 0;
    sh[t] = v;
    __syncthreads();
    for (int o = 1; o < 256; o <<= 1) {
        int add = (t >= o) ? sh[t - o] : 0;
        __syncthreads();
        sh[t] += add;
        __syncthreads();
    }
    if (t < SCB) g_boff[t] = sh[t] - v;
    if (t == 255) g_rowptr[NN] = sh[255];
}

__global__ void scan3_kernel() {
    __shared__ int sh[256];
    int t = threadIdx.x;
    int i = blockIdx.x * 256 + t;
    int v = (i < NN) ? g_cnt[i] : 0;
    sh[t] = v;
    __syncthreads();
    for (int o = 1; o < 256; o <<= 1) {
        int add = (t >= o) ? sh[t - o] : 0;
        __syncthreads();
        sh[t] += add;
        __syncthreads();
    }
    if (i < NN) g_rowptr[i] = g_boff[blockIdx.x] + sh[t] - v;
}

__global__ void fill_kernel(const int* __restrict__ ei) {
    int e = blockIdx.x * blockDim.x + threadIdx.x;
    if (e >= NE) return;
    int s = ei[e];
    int d = ei[NE + e];
    if (s == d) return;
    int pos = g_rowptr[d] + atomicAdd(&g_fill[d], 1);
    g_col[pos] = s;
    g_ew[pos] = g_dinv[s] * g_dinv[d];
}

// ---------------------------------------------------------------------------
// Register-tiled SGEMM with f32x2 packed FMAs.
// Out[N, NOUT] = A[N, K] @ W[NOUT, K]^T ; optional blend epilogue.
// A tile stored transposed in SMEM so row-pairs load as float2.
// ---------------------------------------------------------------------------
template <int K, int NOUT, int TM, int TN, int TX, int TY>
__global__ void gemm_kernel(const float* __restrict__ A,
                            const float* __restrict__ Wg,
                            float* __restrict__ Out,
                            const float* __restrict__ blendSrc,
                            float beta) {
    constexpr int BM = TM * TY;       // 128
    constexpr int NT = TX * TY;       // 256
    constexpr int TP = TM / 2;        // row pairs per thread
    __shared__ __align__(16) float xs_t[16][BM + 2];
    __shared__ __align__(16) float ws[16][NOUT];

    int tid = threadIdx.x;
    int tx = tid % TX;
    int ty = tid / TX;
    int rowbase = blockIdx.x * BM;

    unsigned long long acc2[TP][TN];
#pragma unroll
    for (int r = 0; r < TP; r++)
#pragma unroll
        for (int c = 0; c < TN; c++) acc2[r][c] = 0ull;

    for (int k0 = 0; k0 < K; k0 += 16) {
        __syncthreads();
        for (int i = tid; i < BM * 16; i += NT) {
            int r = i >> 4, c = i & 15;
            int row = rowbase + r;
            xs_t[c][r] = (row < NN) ? A[(size_t)row * K + k0 + c] : 0.f;
        }
        for (int i = tid; i < 16 * NOUT; i += NT) {
            int kk = i % 16, n = i / 16;
            ws[kk][n] = Wg[(size_t)n * K + k0 + kk];
        }
        __syncthreads();
#pragma unroll
        for (int kk = 0; kk < 16; kk++) {
            unsigned long long a2[TP];
            const float2* arow = (const float2*)&xs_t[kk][ty * TM];
#pragma unroll
            for (int r = 0; r < TP; r++) {
                float2 av = arow[r];
                asm("mov.b64 %0, {%1, %2};" : "=l"(a2[r]) : "f"(av.x), "f"(av.y));
            }
            unsigned long long b2[TN];
#pragma unroll
            for (int c = 0; c < TN; c++) b2[c] = packrep(ws[kk][tx * TN + c]);
#pragma unroll
            for (int r = 0; r < TP; r++)
#pragma unroll
                for (int c = 0; c < TN; c++) ffma2(acc2[r][c], a2[r], b2[c]);
        }
    }

#pragma unroll
    for (int r = 0; r < TP; r++) {
        int row0 = rowbase + ty * TM + 2 * r;
#pragma unroll
        for (int c = 0; c < TN; c++) {
            int col = tx * TN + c;
            float2 v = unpack2(acc2[r][c]);
            if (row0 < NN) {
                float o = v.x;
                if (beta != 1.f)
                    o = beta * o + (1.f - beta) * blendSrc[(size_t)row0 * NOUT + col];
                Out[(size_t)row0 * NOUT + col] = o;
            }
            if (row0 + 1 < NN) {
                float o = v.y;
                if (beta != 1.f)
                    o = beta * o + (1.f - beta) * blendSrc[(size_t)(row0 + 1) * NOUT + col];
                Out[(size_t)(row0 + 1) * NOUT + col] = o;
            }
        }
    }
}

// ---------------------------------------------------------------------------
// BatchNorm stats, finalize, apply+ReLU
// ---------------------------------------------------------------------------
__global__ void stats_kernel(const float* __restrict__ X,
                             float* __restrict__ sums, float* __restrict__ sq) {
    __shared__ float ss[4][HID];
    __shared__ float qq[4][HID];
    int c = threadIdx.x;
    int ty = threadIdx.y;
    float s = 0.f, q = 0.f;
    for (int r = blockIdx.x * 4 + ty; r < NN; r += gridDim.x * 4) {
        float v = X[(size_t)r * HID + c];
        s += v;
        q += v * v;
    }
    ss[ty][c] = s;
    qq[ty][c] = q;
    __syncthreads();
    if (ty == 0) {
        s = ss[0][c] + ss[1][c] + ss[2][c] + ss[3][c];
        q = qq[0][c] + qq[1][c] + qq[2][c] + qq[3][c];
        atomicAdd(&sums[c], s);
        atomicAdd(&sq[c], q);
    }
}

__global__ void bn_final_kernel(const float* __restrict__ sums,
                                const float* __restrict__ sq) {
    int c = threadIdx.x;
    if (c < HID) {
        const float invN = 1.f / (float)NN;
        float m = sums[c] * invN;
        float v = sq[c] * invN - m * m;
        g_mean[c] = m;
        g_scl[c] = rsqrtf(v + 1e-5f);
    }
}

__global__ void bnrelu_kernel(const float* __restrict__ X, float* __restrict__ Y) {
    int idx = blockIdx.x * blockDim.x + threadIdx.x;
    if (idx >= NN * HID) return;
    int c = idx % HID;
    float v = (X[idx] - g_mean[c]) * g_scl[c];
    Y[idx] = fmaxf(v, 0.f);
}

// ---------------------------------------------------------------------------
// CSR gather SpMM, warp per node, fused epilogues.
// MODE 1: Y = 0.9*(sum + selfw*X) + 0.1*h0   (GCNII residual conv)
// MODE 0: Y = sum + selfw*X                   (plain gcn_conv)
// ---------------------------------------------------------------------------
template <int F, int MODE>
__global__ void gather_kernel(const float* __restrict__ X, float* __restrict__ Y) {
    int node = (blockIdx.x * blockDim.x + threadIdx.x) >> 5;
    int lane = threadIdx.x & 31;
    if (node >= NN) return;
    constexpr int NC = (F + 31) / 32;
    int p   = g_rowptr[node];
    int end = g_rowptr[node + 1];
    float sum[NC];
#pragma unroll
    for (int j = 0; j < NC; j++) sum[j] = 0.f;

    for (; p < end; p++) {
        int c = __ldg(&g_col[p]);
        float w = __ldg(&g_ew[p]);
        const float* row = X + (size_t)c * F;
#pragma unroll
        for (int j = 0; j < NC; j++) {
            int col = lane + 32 * j;
            if ((F & 31) == 0 || col < F) sum[j] += w * __ldg(&row[col]);
        }
    }

    float sw = g_selfw[node];
#pragma unroll
    for (int j = 0; j < NC; j++) {
        int col = lane + 32 * j;
        if ((F & 31) != 0 && col >= F) continue;
        size_t idx = (size_t)node * F + col;
        float v = sum[j] + sw * X[idx];
        if (MODE == 1) v = 0.9f * v + 0.1f * g_h0[idx];
        Y[idx] = v;
    }
}

// ---------------------------------------------------------------------------
extern "C" void kernel_launch(void* const* d_in, const int* in_sizes, int n_in,
                              void* d_out, int out_size) {
    const float* x  = (const float*)d_in[0];
    const int*   ei = (const int*)d_in[1];
    const float* W0 = (const float*)d_in[2];
    const float* W1 = (const float*)d_in[3];
    const float* W2 = (const float*)d_in[4];
    const float* W3 = (const float*)d_in[5];
    float* out = (float*)d_out;

    float *ph0, *pt, *pu, *pb, *pc, *psum, *psq;
    cudaGetSymbolAddress((void**)&ph0, g_h0);
    cudaGetSymbolAddress((void**)&pt, g_t);
    cudaGetSymbolAddress((void**)&pu, g_u);
    cudaGetSymbolAddress((void**)&pb, g_b);
    cudaGetSymbolAddress((void**)&pc, g_c);
    cudaGetSymbolAddress((void**)&psum, g_sum);
    cudaGetSymbolAddress((void**)&psq, g_sq);

    const int gbE = (NE + 255) / 256;
    const int gbN = (NN + 255) / 256;
    const int gbH = (NN * HID + 255) / 256;
    const int gbG = (NN + 127) / 128;
    const int gbW = (NN * 32 + 255) / 256;   // warp-per-node gathers
    dim3 statsBlk(HID, 4);

    // ---- graph prep: degree, CSR build ----
    zero_prep_kernel<<<gbN, 256>>>();
    cnt_kernel<<<gbE, 256>>>(ei);
    fin_deg_kernel<<<gbN, 256>>>();
    scan1_kernel<<<SCB, 256>>>();
    scan2_kernel<<<1, 256>>>();
    scan3_kernel<<<SCB, 256>>>();
    fill_kernel<<<gbE, 256>>>(ei);

    // ---- layer 0: h0 = relu(bn(x @ W0^T)) ----
    gemm_kernel<INC, HID, 8, 6, 16, 16><<<gbG, 256>>>(x, W0, pt, nullptr, 1.f);
    stats_kernel<<<128, statsBlk>>>(pt, psum + 0 * HID, psq + 0 * HID);
    bn_final_kernel<<<1, HID>>>(psum + 0 * HID, psq + 0 * HID);
    bnrelu_kernel<<<gbH, 256>>>(pt, ph0);

    // ---- layer 1 (beta = 0.5) ----
    gemm_kernel<HID, HID, 8, 6, 16, 16><<<gbG, 256>>>(ph0, W1, pt, ph0, 0.5f);
    gather_kernel<HID, 1><<<gbW, 256>>>(pt, pu);
    stats_kernel<<<128, statsBlk>>>(pu, psum + 1 * HID, psq + 1 * HID);
    bn_final_kernel<<<1, HID>>>(psum + 1 * HID, psq + 1 * HID);
    bnrelu_kernel<<<gbH, 256>>>(pu, pb);

    // ---- layer 2 (beta = 0.25) ----
    gemm_kernel<HID, HID, 8, 6, 16, 16><<<gbG, 256>>>(pb, W2, pt, pb, 0.25f);
    gather_kernel<HID, 1><<<gbW, 256>>>(pt, pu);
    stats_kernel<<<128, statsBlk>>>(pu, psum + 2 * HID, psq + 2 * HID);
    bn_final_kernel<<<1, HID>>>(psum + 2 * HID, psq + 2 * HID);
    bnrelu_kernel<<<gbH, 256>>>(pu, pb);

    // ---- final: out = spmm(b @ W3^T) ----
    gemm_kernel<HID, OUTC, 4, 5, 8, 32><<<gbG, 256>>>(pb, W3, pc, nullptr, 1.f);
    gather_kernel<OUTC, 0><<<gbW, 256>>>(pc, out);
}

// round 4
// speedup vs baseline: 1.9416x; 1.1309x over previous
#include <cuda_runtime.h>
#include <cuda_bf16.h>

#define NN 50000
#define NE 800000
#define INC 128
#define HID 96
#define OUTC 40
#define SCB 196   // scan blocks: 196*256 = 50176 >= NN

__device__ float g_dinv[NN];
__device__ float g_selfw[NN];
__device__ int   g_cnt[NN];
__device__ int   g_fill[NN];
__device__ int   g_rowptr[NN + 1];
__device__ int   g_bsum[256];
__device__ int   g_boff[256];
__device__ int   g_col[NE];
__device__ float g_ew[NE];
__device__ float g_t [NN * HID];   // layer-0 raw GEMM output (h0 source)
__device__ float g_t2[NN * HID];   // blended GEMM output per layer
__device__ float g_u [NN * HID];   // conv_resi output per layer
__device__ float g_c [NN * OUTC];
__device__ float g_sum[3 * HID];
__device__ float g_sq [3 * HID];
__device__ float g_meanL[3][HID];
__device__ float g_sclL [3][HID];

// ---------------------------------------------------------------------------
// f32x2 packed math helpers
// ---------------------------------------------------------------------------
__device__ __forceinline__ void ffma2(unsigned long long& acc,
                                      unsigned long long a2,
                                      unsigned long long b2) {
    asm("fma.rn.f32x2 %0, %1, %2, %3;" : "=l"(acc) : "l"(a2), "l"(b2), "l"(acc));
}
__device__ __forceinline__ unsigned long long packrep(float x) {
    unsigned long long r;
    asm("mov.b64 %0, {%1, %1};" : "=l"(r) : "f"(x));
    return r;
}
__device__ __forceinline__ float2 unpack2(unsigned long long v) {
    float2 r;
    asm("mov.b64 {%0, %1}, %2;" : "=f"(r.x), "=f"(r.y) : "l"(v));
    return r;
}

// ---------------------------------------------------------------------------
// Prep
// ---------------------------------------------------------------------------
__global__ void zero_prep_kernel() {
    int i = blockIdx.x * blockDim.x + threadIdx.x;
    if (i < NN) { g_cnt[i] = 0; g_fill[i] = 0; }
    if (i < 3 * HID) { g_sum[i] = 0.f; g_sq[i] = 0.f; }
}

__global__ void cnt_kernel(const int* __restrict__ ei) {
    int e = blockIdx.x * blockDim.x + threadIdx.x;
    if (e >= NE) return;
    int s = ei[e];
    int d = ei[NE + e];
    if (s != d) atomicAdd(&g_cnt[d], 1);
}

// ---------------------------------------------------------------------------
// 3-kernel exclusive scan of g_cnt -> g_rowptr (+ degree finalize in scan3)
// ---------------------------------------------------------------------------
__global__ void scan1_kernel() {
    __shared__ int sh[256];
    int i = blockIdx.x * 256 + threadIdx.x;
    sh[threadIdx.x] = (i < NN) ? g_cnt[i] : 0;
    __syncthreads();
    for (int o = 128; o > 0; o >>= 1) {
        if (threadIdx.x < o) sh[threadIdx.x] += sh[threadIdx.x + o];
        __syncthreads();
    }
    if (threadIdx.x == 0) g_bsum[blockIdx.x] = sh[0];
}

__global__ void scan2_kernel() {
    __shared__ int sh[256];
    int t = threadIdx.x;
    int v = (t < SCB) ? g_bsum[t] : 0;
    sh[t] = v;
    __syncthreads();
    for (int o = 1; o < 256; o <<= 1) {
        int add = (t >= o) ? sh[t - o] : 0;
        __syncthreads();
        sh[t] += add;
        __syncthreads();
    }
    if (t < SCB) g_boff[t] = sh[t] - v;
    if (t == 255) g_rowptr[NN] = sh[255];
}

__global__ void scan3_kernel() {
    __shared__ int sh[256];
    int t = threadIdx.x;
    int i = blockIdx.x * 256 + t;
    int v = (i < NN) ? g_cnt[i] : 0;
    sh[t] = v;
    __syncthreads();
    for (int o = 1; o < 256; o <<= 1) {
        int add = (t >= o) ? sh[t - o] : 0;
        __syncthreads();
        sh[t] += add;
        __syncthreads();
    }
    if (i < NN) {
        g_rowptr[i] = g_boff[blockIdx.x] + sh[t] - v;
        float d = (float)v + 1.f;
        g_dinv[i]  = rsqrtf(d);
        g_selfw[i] = 1.f / d;
    }
}

__global__ void fill_kernel(const int* __restrict__ ei) {
    int e = blockIdx.x * blockDim.x + threadIdx.x;
    if (e >= NE) return;
    int s = ei[e];
    int d = ei[NE + e];
    if (s == d) return;
    int pos = g_rowptr[d] + atomicAdd(&g_fill[d], 1);
    g_col[pos] = s;
    g_ew[pos] = g_dinv[s] * g_dinv[d];
}

// ---------------------------------------------------------------------------
// Register-tiled SGEMM (f32x2), optional fused input BN+ReLU and blend.
// Out[N, NOUT] = normA(A)[N, K] @ W[NOUT, K]^T
//   NORM=1: normA(a, f) = relu((a - mean[f]) * scl[f])
//   beta != 1: Out = beta*acc + (1-beta)*normA(blendSrc)   (requires NOUT == K feats)
// ---------------------------------------------------------------------------
template <int K, int NOUT, int TM, int TN, int TX, int TY, int NORM>
__global__ void gemm_kernel(const float* __restrict__ A,
                            const float* __restrict__ Wg,
                            float* __restrict__ Out,
                            const float* __restrict__ blendSrc,
                            const float* __restrict__ mean,
                            const float* __restrict__ scl,
                            float beta) {
    constexpr int BM = TM * TY;
    constexpr int NT = TX * TY;
    constexpr int TP = TM / 2;
    __shared__ __align__(16) float xs_t[16][BM + 2];
    __shared__ __align__(16) float ws[16][NOUT];

    int tid = threadIdx.x;
    int tx = tid % TX;
    int ty = tid / TX;
    int rowbase = blockIdx.x * BM;

    unsigned long long acc2[TP][TN];
#pragma unroll
    for (int r = 0; r < TP; r++)
#pragma unroll
        for (int c = 0; c < TN; c++) acc2[r][c] = 0ull;

    for (int k0 = 0; k0 < K; k0 += 16) {
        __syncthreads();
        for (int i = tid; i < BM * 16; i += NT) {
            int r = i >> 4, c = i & 15;
            int row = rowbase + r;
            float v = (row < NN) ? A[(size_t)row * K + k0 + c] : 0.f;
            if (NORM) v = fmaxf((v - __ldg(&mean[k0 + c])) * __ldg(&scl[k0 + c]), 0.f);
            xs_t[c][r] = v;
        }
        for (int i = tid; i < 16 * NOUT; i += NT) {
            int kk = i % 16, n = i / 16;
            ws[kk][n] = Wg[(size_t)n * K + k0 + kk];
        }
        __syncthreads();
#pragma unroll
        for (int kk = 0; kk < 16; kk++) {
            unsigned long long a2[TP];
            const float2* arow = (const float2*)&xs_t[kk][ty * TM];
#pragma unroll
            for (int r = 0; r < TP; r++) {
                float2 av = arow[r];
                asm("mov.b64 %0, {%1, %2};" : "=l"(a2[r]) : "f"(av.x), "f"(av.y));
            }
            unsigned long long b2[TN];
#pragma unroll
            for (int c = 0; c < TN; c++) b2[c] = packrep(ws[kk][tx * TN + c]);
#pragma unroll
            for (int r = 0; r < TP; r++)
#pragma unroll
                for (int c = 0; c < TN; c++) ffma2(acc2[r][c], a2[r], b2[c]);
        }
    }

#pragma unroll
    for (int r = 0; r < TP; r++) {
        int row0 = rowbase + ty * TM + 2 * r;
#pragma unroll
        for (int c = 0; c < TN; c++) {
            int col = tx * TN + c;
            float2 v = unpack2(acc2[r][c]);
#pragma unroll
            for (int half = 0; half < 2; half++) {
                int row = row0 + half;
                if (row >= NN) continue;
                float o = half ? v.y : v.x;
                if (beta != 1.f) {
                    float b = blendSrc[(size_t)row * NOUT + col];
                    if (NORM) b = fmaxf((b - mean[col]) * scl[col], 0.f);
                    o = beta * o + (1.f - beta) * b;
                }
                Out[(size_t)row * NOUT + col] = o;
            }
        }
    }
}

// ---------------------------------------------------------------------------
// BatchNorm stats + finalize
// ---------------------------------------------------------------------------
__global__ void stats_kernel(const float* __restrict__ X,
                             float* __restrict__ sums, float* __restrict__ sq) {
    __shared__ float ss[4][HID];
    __shared__ float qq[4][HID];
    int c = threadIdx.x;
    int ty = threadIdx.y;
    float s = 0.f, q = 0.f;
    for (int r = blockIdx.x * 4 + ty; r < NN; r += gridDim.x * 4) {
        float v = X[(size_t)r * HID + c];
        s += v;
        q += v * v;
    }
    ss[ty][c] = s;
    qq[ty][c] = q;
    __syncthreads();
    if (ty == 0) {
        s = ss[0][c] + ss[1][c] + ss[2][c] + ss[3][c];
        q = qq[0][c] + qq[1][c] + qq[2][c] + qq[3][c];
        atomicAdd(&sums[c], s);
        atomicAdd(&sq[c], q);
    }
}

__global__ void bn_final_kernel(const float* __restrict__ sums,
                                const float* __restrict__ sq,
                                float* __restrict__ mean,
                                float* __restrict__ scl) {
    int c = threadIdx.x;
    if (c < HID) {
        const float invN = 1.f / (float)NN;
        float m = sums[c] * invN;
        float v = sq[c] * invN - m * m;
        mean[c] = m;
        scl[c] = rsqrtf(v + 1e-5f);
    }
}

// ---------------------------------------------------------------------------
// CSR gather SpMM, warp per node, edge loop unrolled x4 for MLP.
// MODE 1: Y = 0.9*(sum + selfw*X) + 0.1*relu(bn0(h0raw))
// MODE 0: Y = sum + selfw*X
// ---------------------------------------------------------------------------
template <int F, int MODE>
__global__ void gather_kernel(const float* __restrict__ X, float* __restrict__ Y,
                              const float* __restrict__ h0raw,
                              const float* __restrict__ mean0,
                              const float* __restrict__ scl0) {
    int node = (blockIdx.x * blockDim.x + threadIdx.x) >> 5;
    int lane = threadIdx.x & 31;
    if (node >= NN) return;
    constexpr int NC = (F + 31) / 32;
    int p   = g_rowptr[node];
    int end = g_rowptr[node + 1];
    float sum[NC];
#pragma unroll
    for (int j = 0; j < NC; j++) sum[j] = 0.f;

    for (; p + 4 <= end; p += 4) {
        int   c0 = __ldg(&g_col[p]),     c1 = __ldg(&g_col[p + 1]);
        int   c2 = __ldg(&g_col[p + 2]), c3 = __ldg(&g_col[p + 3]);
        float w0 = __ldg(&g_ew[p]),      w1 = __ldg(&g_ew[p + 1]);
        float w2 = __ldg(&g_ew[p + 2]),  w3 = __ldg(&g_ew[p + 3]);
        const float* r0 = X + (size_t)c0 * F;
        const float* r1 = X + (size_t)c1 * F;
        const float* r2 = X + (size_t)c2 * F;
        const float* r3 = X + (size_t)c3 * F;
        float v0[NC], v1[NC], v2[NC], v3[NC];
#pragma unroll
        for (int j = 0; j < NC; j++) {
            int col = lane + 32 * j;
            bool ok = (F & 31) == 0 || col < F;
            v0[j] = ok ? __ldg(&r0[col]) : 0.f;
            v1[j] = ok ? __ldg(&r1[col]) : 0.f;
            v2[j] = ok ? __ldg(&r2[col]) : 0.f;
            v3[j] = ok ? __ldg(&r3[col]) : 0.f;
        }
#pragma unroll
        for (int j = 0; j < NC; j++)
            sum[j] += w0 * v0[j] + w1 * v1[j] + w2 * v2[j] + w3 * v3[j];
    }
    for (; p < end; p++) {
        int c = __ldg(&g_col[p]);
        float w = __ldg(&g_ew[p]);
        const float* row = X + (size_t)c * F;
#pragma unroll
        for (int j = 0; j < NC; j++) {
            int col = lane + 32 * j;
            if ((F & 31) == 0 || col < F) sum[j] += w * __ldg(&row[col]);
        }
    }

    float sw = g_selfw[node];
#pragma unroll
    for (int j = 0; j < NC; j++) {
        int col = lane + 32 * j;
        if ((F & 31) != 0 && col >= F) continue;
        size_t idx = (size_t)node * F + col;
        float v = sum[j] + sw * X[idx];
        if (MODE == 1) {
            float h0 = fmaxf((h0raw[idx] - mean0[col]) * scl0[col], 0.f);
            v = 0.9f * v + 0.1f * h0;
        }
        Y[idx] = v;
    }
}

// ---------------------------------------------------------------------------
extern "C" void kernel_launch(void* const* d_in, const int* in_sizes, int n_in,
                              void* d_out, int out_size) {
    const float* x  = (const float*)d_in[0];
    const int*   ei = (const int*)d_in[1];
    const float* W0 = (const float*)d_in[2];
    const float* W1 = (const float*)d_in[3];
    const float* W2 = (const float*)d_in[4];
    const float* W3 = (const float*)d_in[5];
    float* out = (float*)d_out;

    float *pt, *pt2, *pu, *pc, *psum, *psq, *pmean, *pscl;
    cudaGetSymbolAddress((void**)&pt, g_t);
    cudaGetSymbolAddress((void**)&pt2, g_t2);
    cudaGetSymbolAddress((void**)&pu, g_u);
    cudaGetSymbolAddress((void**)&pc, g_c);
    cudaGetSymbolAddress((void**)&psum, g_sum);
    cudaGetSymbolAddress((void**)&psq, g_sq);
    cudaGetSymbolAddress((void**)&pmean, g_meanL);
    cudaGetSymbolAddress((void**)&pscl, g_sclL);

    const int gbE = (NE + 255) / 256;
    const int gbN = (NN + 255) / 256;
    const int gbG = (NN + 127) / 128;
    const int gbW = (NN * 32 + 511) / 512;
    dim3 statsBlk(HID, 4);

    float* m0 = pmean + 0 * HID; float* s0 = pscl + 0 * HID;
    float* m1 = pmean + 1 * HID; float* s1 = pscl + 1 * HID;
    float* m2 = pmean + 2 * HID; float* s2 = pscl + 2 * HID;

    // ---- graph prep ----
    zero_prep_kernel<<<gbN, 256>>>();
    cnt_kernel<<<gbE, 256>>>(ei);
    scan1_kernel<<<SCB, 256>>>();
    scan2_kernel<<<1, 256>>>();
    scan3_kernel<<<SCB, 256>>>();
    fill_kernel<<<gbE, 256>>>(ei);

    // ---- layer 0: t = x @ W0^T ; stats -> (m0, s0). h0 = relu(bn0(t)) stays virtual.
    gemm_kernel<INC, HID, 8, 6, 16, 16, 0><<<gbG, 256>>>(x, W0, pt, nullptr, nullptr, nullptr, 1.f);
    stats_kernel<<<128, statsBlk>>>(pt, psum + 0 * HID, psq + 0 * HID);
    bn_final_kernel<<<1, HID>>>(psum + 0 * HID, psq + 0 * HID, m0, s0);

    // ---- layer 1 (beta = 0.5): t2 = 0.5*bn0relu(t)@W1^T + 0.5*bn0relu(t)
    gemm_kernel<HID, HID, 8, 6, 16, 16, 1><<<gbG, 256>>>(pt, W1, pt2, pt, m0, s0, 0.5f);
    gather_kernel<HID, 1><<<gbW, 512>>>(pt2, pu, pt, m0, s0);
    stats_kernel<<<128, statsBlk>>>(pu, psum + 1 * HID, psq + 1 * HID);
    bn_final_kernel<<<1, HID>>>(psum + 1 * HID, psq + 1 * HID, m1, s1);

    // ---- layer 2 (beta = 0.25): input raw = u, stats (m1, s1)
    gemm_kernel<HID, HID, 8, 6, 16, 16, 1><<<gbG, 256>>>(pu, W2, pt2, pu, m1, s1, 0.25f);
    gather_kernel<HID, 1><<<gbW, 512>>>(pt2, pu, pt, m0, s0);
    stats_kernel<<<128, statsBlk>>>(pu, psum + 2 * HID, psq + 2 * HID);
    bn_final_kernel<<<1, HID>>>(psum + 2 * HID, psq + 2 * HID, m2, s2);

    // ---- final: c = bn2relu(u) @ W3^T ; out = spmm(c)
    gemm_kernel<HID, OUTC, 4, 5, 8, 32, 1><<<gbG, 256>>>(pu, W3, pc, nullptr, m2, s2, 1.f);
    gather_kernel<OUTC, 0><<<gbW, 512>>>(pc, out, nullptr, nullptr, nullptr);
}

// round 5
// speedup vs baseline: 2.0807x; 1.0717x over previous
#include <cuda_runtime.h>
#include <cuda_bf16.h>

#define NN 50000
#define NE 800000
#define INC 128
#define HID 96
#define OUTC 40
#define SCB 196   // scan blocks: 196*256 = 50176 >= NN

__device__ float g_dinv[NN];
__device__ float g_selfw[NN];
__device__ int   g_cnt[NN];
__device__ int   g_fill[NN];
__device__ int   g_rowptr[NN + 1];
__device__ int   g_bsum[256];
__device__ int   g_boff[256];
__device__ int   g_col[NE];
__device__ float g_ew[NE];
__device__ float g_t [NN * HID];   // layer-0 raw GEMM output (h0 source)
__device__ float g_t2[NN * HID];   // blended GEMM output per layer
__device__ float g_u [NN * HID];   // conv_resi output per layer
__device__ float g_c [NN * OUTC];
__device__ float g_sum[3 * HID];
__device__ float g_sq [3 * HID];
__device__ float g_meanL[3][HID];
__device__ float g_sclL [3][HID];

// ---------------------------------------------------------------------------
// f32x2 packed math helpers
// ---------------------------------------------------------------------------
__device__ __forceinline__ void ffma2(unsigned long long& acc,
                                      unsigned long long a2,
                                      unsigned long long b2) {
    asm("fma.rn.f32x2 %0, %1, %2, %3;" : "=l"(acc) : "l"(a2), "l"(b2), "l"(acc));
}
__device__ __forceinline__ unsigned long long packrep(float x) {
    unsigned long long r;
    asm("mov.b64 %0, {%1, %1};" : "=l"(r) : "f"(x));
    return r;
}
__device__ __forceinline__ float2 unpack2(unsigned long long v) {
    float2 r;
    asm("mov.b64 {%0, %1}, %2;" : "=f"(r.x), "=f"(r.y) : "l"(v));
    return r;
}

// ---------------------------------------------------------------------------
// Prep
// ---------------------------------------------------------------------------
__global__ void zero_prep_kernel() {
    int i = blockIdx.x * blockDim.x + threadIdx.x;
    if (i < NN) { g_cnt[i] = 0; g_fill[i] = 0; }
    if (i < 3 * HID) { g_sum[i] = 0.f; g_sq[i] = 0.f; }
}

__global__ void cnt_kernel(const int* __restrict__ ei) {
    int e = blockIdx.x * blockDim.x + threadIdx.x;
    if (e >= NE) return;
    int s = ei[e];
    int d = ei[NE + e];
    if (s != d) atomicAdd(&g_cnt[d], 1);
}

__global__ void scan1_kernel() {
    __shared__ int sh[256];
    int i = blockIdx.x * 256 + threadIdx.x;
    sh[threadIdx.x] = (i < NN) ? g_cnt[i] : 0;
    __syncthreads();
    for (int o = 128; o > 0; o >>= 1) {
        if (threadIdx.x < o) sh[threadIdx.x] += sh[threadIdx.x + o];
        __syncthreads();
    }
    if (threadIdx.x == 0) g_bsum[blockIdx.x] = sh[0];
}

__global__ void scan2_kernel() {
    __shared__ int sh[256];
    int t = threadIdx.x;
    int v = (t < SCB) ? g_bsum[t] : 0;
    sh[t] = v;
    __syncthreads();
    for (int o = 1; o < 256; o <<= 1) {
        int add = (t >= o) ? sh[t - o] : 0;
        __syncthreads();
        sh[t] += add;
        __syncthreads();
    }
    if (t < SCB) g_boff[t] = sh[t] - v;
    if (t == 255) g_rowptr[NN] = sh[255];
}

__global__ void scan3_kernel() {
    __shared__ int sh[256];
    int t = threadIdx.x;
    int i = blockIdx.x * 256 + t;
    int v = (i < NN) ? g_cnt[i] : 0;
    sh[t] = v;
    __syncthreads();
    for (int o = 1; o < 256; o <<= 1) {
        int add = (t >= o) ? sh[t - o] : 0;
        __syncthreads();
        sh[t] += add;
        __syncthreads();
    }
    if (i < NN) {
        g_rowptr[i] = g_boff[blockIdx.x] + sh[t] - v;
        float d = (float)v + 1.f;
        g_dinv[i]  = rsqrtf(d);
        g_selfw[i] = 1.f / d;
    }
}

__global__ void fill_kernel(const int* __restrict__ ei) {
    int e = blockIdx.x * blockDim.x + threadIdx.x;
    if (e >= NE) return;
    int s = ei[e];
    int d = ei[NE + e];
    if (s == d) return;
    int pos = g_rowptr[d] + atomicAdd(&g_fill[d], 1);
    g_col[pos] = s;
    g_ew[pos] = g_dinv[s] * g_dinv[d];
}

// ---------------------------------------------------------------------------
// Register-tiled SGEMM (f32x2). Optional fused input BN+ReLU (NORM),
// GCNII blend (beta != 1), and fused column stats of Out (STATS).
// ---------------------------------------------------------------------------
template <int K, int NOUT, int TM, int TN, int TX, int TY, int NORM, int STATS>
__global__ void gemm_kernel(const float* __restrict__ A,
                            const float* __restrict__ Wg,
                            float* __restrict__ Out,
                            const float* __restrict__ blendSrc,
                            const float* __restrict__ mean,
                            const float* __restrict__ scl,
                            float beta,
                            float* __restrict__ sums,
                            float* __restrict__ sq) {
    constexpr int BM = TM * TY;
    constexpr int NT = TX * TY;
    constexpr int TP = TM / 2;
    __shared__ __align__(16) float xs_t[16][BM + 2];
    __shared__ __align__(16) float ws[16][NOUT];
    __shared__ float ssum[NOUT];
    __shared__ float ssq[NOUT];

    int tid = threadIdx.x;
    int tx = tid % TX;
    int ty = tid / TX;
    int rowbase = blockIdx.x * BM;

    if (STATS) {
        for (int i = tid; i < NOUT; i += NT) { ssum[i] = 0.f; ssq[i] = 0.f; }
    }

    unsigned long long acc2[TP][TN];
#pragma unroll
    for (int r = 0; r < TP; r++)
#pragma unroll
        for (int c = 0; c < TN; c++) acc2[r][c] = 0ull;

    for (int k0 = 0; k0 < K; k0 += 16) {
        __syncthreads();
        // A tile: float4 global loads, transposed scalar SMEM stores
        for (int i = tid; i < BM * 4; i += NT) {
            int r = i >> 2, c4 = (i & 3) * 4;
            int row = rowbase + r;
            float4 v = (row < NN)
                ? __ldg((const float4*)&A[(size_t)row * K + k0 + c4])
                : make_float4(0.f, 0.f, 0.f, 0.f);
            if (NORM) {
                float4 m = __ldg((const float4*)&mean[k0 + c4]);
                float4 s = __ldg((const float4*)&scl[k0 + c4]);
                v.x = fmaxf((v.x - m.x) * s.x, 0.f);
                v.y = fmaxf((v.y - m.y) * s.y, 0.f);
                v.z = fmaxf((v.z - m.z) * s.z, 0.f);
                v.w = fmaxf((v.w - m.w) * s.w, 0.f);
            }
            xs_t[c4 + 0][r] = v.x;
            xs_t[c4 + 1][r] = v.y;
            xs_t[c4 + 2][r] = v.z;
            xs_t[c4 + 3][r] = v.w;
        }
        for (int i = tid; i < 16 * NOUT; i += NT) {
            int kk = i % 16, n = i / 16;
            ws[kk][n] = Wg[(size_t)n * K + k0 + kk];
        }
        __syncthreads();
#pragma unroll
        for (int kk = 0; kk < 16; kk++) {
            unsigned long long a2[TP];
            const float2* arow = (const float2*)&xs_t[kk][ty * TM];
#pragma unroll
            for (int r = 0; r < TP; r++) {
                float2 av = arow[r];
                asm("mov.b64 %0, {%1, %2};" : "=l"(a2[r]) : "f"(av.x), "f"(av.y));
            }
            unsigned long long b2[TN];
#pragma unroll
            for (int c = 0; c < TN; c++) b2[c] = packrep(ws[kk][tx * TN + c]);
#pragma unroll
            for (int r = 0; r < TP; r++)
#pragma unroll
                for (int c = 0; c < TN; c++) ffma2(acc2[r][c], a2[r], b2[c]);
        }
    }

    float colsum[TN], colsq[TN];
    if (STATS) {
#pragma unroll
        for (int c = 0; c < TN; c++) { colsum[c] = 0.f; colsq[c] = 0.f; }
    }

#pragma unroll
    for (int r = 0; r < TP; r++) {
        int row0 = rowbase + ty * TM + 2 * r;
#pragma unroll
        for (int c = 0; c < TN; c++) {
            int col = tx * TN + c;
            float2 v = unpack2(acc2[r][c]);
#pragma unroll
            for (int half = 0; half < 2; half++) {
                int row = row0 + half;
                if (row >= NN) continue;
                float o = half ? v.y : v.x;
                if (beta != 1.f) {
                    float b = blendSrc[(size_t)row * NOUT + col];
                    if (NORM) b = fmaxf((b - mean[col]) * scl[col], 0.f);
                    o = beta * o + (1.f - beta) * b;
                }
                Out[(size_t)row * NOUT + col] = o;
                if (STATS) { colsum[c] += o; colsq[c] += o * o; }
            }
        }
    }

    if (STATS) {
#pragma unroll
        for (int c = 0; c < TN; c++) {
            atomicAdd(&ssum[tx * TN + c], colsum[c]);
            atomicAdd(&ssq[tx * TN + c], colsq[c]);
        }
        __syncthreads();
        for (int i = tid; i < NOUT; i += NT) {
            atomicAdd(&sums[i], ssum[i]);
            atomicAdd(&sq[i], ssq[i]);
        }
    }
}

// ---------------------------------------------------------------------------
// BN finalize
// ---------------------------------------------------------------------------
__global__ void bn_final_kernel(const float* __restrict__ sums,
                                const float* __restrict__ sq,
                                float* __restrict__ mean,
                                float* __restrict__ scl) {
    int c = threadIdx.x;
    if (c < HID) {
        const float invN = 1.f / (float)NN;
        float m = sums[c] * invN;
        float v = sq[c] * invN - m * m;
        mean[c] = m;
        scl[c] = rsqrtf(v + 1e-5f);
    }
}

// ---------------------------------------------------------------------------
// CSR gather SpMM, warp per node, float4 lanes, edge loop unrolled x4.
// MODE 1: Y = 0.9*(sum + selfw*X) + 0.1*relu(bn0(h0raw)), fused col stats of Y
// MODE 0: Y = sum + selfw*X
// Grid must cover exactly NN warps (3125 blocks x 16 warps).
// ---------------------------------------------------------------------------
template <int F, int MODE>
__global__ void gather_kernel(const float* __restrict__ X, float* __restrict__ Y,
                              const float* __restrict__ h0raw,
                              const float* __restrict__ mean0,
                              const float* __restrict__ scl0,
                              float* __restrict__ sums,
                              float* __restrict__ sq) {
    constexpr int NV = F / 4;  // active lanes (24 for F=96, 10 for F=40)
    __shared__ float ssum[HID];
    __shared__ float ssq[HID];
    int tid = threadIdx.x;
    if (MODE == 1) {
        if (tid < F) { ssum[tid] = 0.f; ssq[tid] = 0.f; }
        __syncthreads();
    }
    int node = blockIdx.x * (blockDim.x >> 5) + (tid >> 5);
    int lane = tid & 31;
    bool act = lane < NV;
    const float4* Xv = (const float4*)X;

    float4 sum = make_float4(0.f, 0.f, 0.f, 0.f);
    int p   = g_rowptr[node];
    int end = g_rowptr[node + 1];

    for (; p + 4 <= end; p += 4) {
        int   c0 = __ldg(&g_col[p]),     c1 = __ldg(&g_col[p + 1]);
        int   c2 = __ldg(&g_col[p + 2]), c3 = __ldg(&g_col[p + 3]);
        float w0 = __ldg(&g_ew[p]),      w1 = __ldg(&g_ew[p + 1]);
        float w2 = __ldg(&g_ew[p + 2]),  w3 = __ldg(&g_ew[p + 3]);
        if (act) {
            float4 v0 = __ldg(&Xv[(size_t)c0 * NV + lane]);
            float4 v1 = __ldg(&Xv[(size_t)c1 * NV + lane]);
            float4 v2 = __ldg(&Xv[(size_t)c2 * NV + lane]);
            float4 v3 = __ldg(&Xv[(size_t)c3 * NV + lane]);
            sum.x += w0 * v0.x + w1 * v1.x + w2 * v2.x + w3 * v3.x;
            sum.y += w0 * v0.y + w1 * v1.y + w2 * v2.y + w3 * v3.y;
            sum.z += w0 * v0.z + w1 * v1.z + w2 * v2.z + w3 * v3.z;
            sum.w += w0 * v0.w + w1 * v1.w + w2 * v2.w + w3 * v3.w;
        }
    }
    for (; p < end; p++) {
        int c = __ldg(&g_col[p]);
        float w = __ldg(&g_ew[p]);
        if (act) {
            float4 v = __ldg(&Xv[(size_t)c * NV + lane]);
            sum.x += w * v.x; sum.y += w * v.y;
            sum.z += w * v.z; sum.w += w * v.w;
        }
    }

    if (act) {
        float sw = g_selfw[node];
        float4 xv = __ldg(&Xv[(size_t)node * NV + lane]);
        float4 v;
        v.x = sum.x + sw * xv.x;
        v.y = sum.y + sw * xv.y;
        v.z = sum.z + sw * xv.z;
        v.w = sum.w + sw * xv.w;
        if (MODE == 1) {
            float4 m  = __ldg(&((const float4*)mean0)[lane]);
            float4 s  = __ldg(&((const float4*)scl0)[lane]);
            float4 hr = __ldg(&((const float4*)h0raw)[(size_t)node * NV + lane]);
            v.x = 0.9f * v.x + 0.1f * fmaxf((hr.x - m.x) * s.x, 0.f);
            v.y = 0.9f * v.y + 0.1f * fmaxf((hr.y - m.y) * s.y, 0.f);
            v.z = 0.9f * v.z + 0.1f * fmaxf((hr.z - m.z) * s.z, 0.f);
            v.w = 0.9f * v.w + 0.1f * fmaxf((hr.w - m.w) * s.w, 0.f);
        }
        ((float4*)Y)[(size_t)node * NV + lane] = v;
        if (MODE == 1) {
            int col = lane * 4;
            atomicAdd(&ssum[col + 0], v.x);
            atomicAdd(&ssum[col + 1], v.y);
            atomicAdd(&ssum[col + 2], v.z);
            atomicAdd(&ssum[col + 3], v.w);
            atomicAdd(&ssq[col + 0], v.x * v.x);
            atomicAdd(&ssq[col + 1], v.y * v.y);
            atomicAdd(&ssq[col + 2], v.z * v.z);
            atomicAdd(&ssq[col + 3], v.w * v.w);
        }
    }

    if (MODE == 1) {
        __syncthreads();
        if (tid < F) {
            atomicAdd(&sums[tid], ssum[tid]);
            atomicAdd(&sq[tid], ssq[tid]);
        }
    }
}

// ---------------------------------------------------------------------------
extern "C" void kernel_launch(void* const* d_in, const int* in_sizes, int n_in,
                              void* d_out, int out_size) {
    const float* x  = (const float*)d_in[0];
    const int*   ei = (const int*)d_in[1];
    const float* W0 = (const float*)d_in[2];
    const float* W1 = (const float*)d_in[3];
    const float* W2 = (const float*)d_in[4];
    const float* W3 = (const float*)d_in[5];
    float* out = (float*)d_out;

    float *pt, *pt2, *pu, *pc, *psum, *psq, *pmean, *pscl;
    cudaGetSymbolAddress((void**)&pt, g_t);
    cudaGetSymbolAddress((void**)&pt2, g_t2);
    cudaGetSymbolAddress((void**)&pu, g_u);
    cudaGetSymbolAddress((void**)&pc, g_c);
    cudaGetSymbolAddress((void**)&psum, g_sum);
    cudaGetSymbolAddress((void**)&psq, g_sq);
    cudaGetSymbolAddress((void**)&pmean, g_meanL);
    cudaGetSymbolAddress((void**)&pscl, g_sclL);

    const int gbE = (NE + 255) / 256;
    const int gbN = (NN + 255) / 256;
    const int gbG = (NN + 127) / 128;
    const int gbW = NN / 16;  // 3125 blocks x 16 warps = exactly NN warps

    float* m0 = pmean + 0 * HID; float* s0 = pscl + 0 * HID;
    float* m1 = pmean + 1 * HID; float* s1 = pscl + 1 * HID;
    float* m2 = pmean + 2 * HID; float* s2 = pscl + 2 * HID;

    // ---- prep + layer-0 GEMM (slot 4 for the ncu capture window) ----
    zero_prep_kernel<<<gbN, 256>>>();
    cnt_kernel<<<gbE, 256>>>(ei);
    scan1_kernel<<<SCB, 256>>>();
    gemm_kernel<INC, HID, 8, 6, 16, 16, 0, 1><<<gbG, 256>>>(
        x, W0, pt, nullptr, nullptr, nullptr, 1.f, psum + 0 * HID, psq + 0 * HID);
    scan2_kernel<<<1, 256>>>();
    scan3_kernel<<<SCB, 256>>>();
    fill_kernel<<<gbE, 256>>>(ei);
    bn_final_kernel<<<1, HID>>>(psum + 0 * HID, psq + 0 * HID, m0, s0);

    // ---- layer 1 (beta = 0.5) ----
    gemm_kernel<HID, HID, 8, 6, 16, 16, 1, 0><<<gbG, 256>>>(
        pt, W1, pt2, pt, m0, s0, 0.5f, nullptr, nullptr);
    gather_kernel<HID, 1><<<gbW, 512>>>(pt2, pu, pt, m0, s0, psum + 1 * HID, psq + 1 * HID);
    bn_final_kernel<<<1, HID>>>(psum + 1 * HID, psq + 1 * HID, m1, s1);

    // ---- layer 2 (beta = 0.25) ----
    gemm_kernel<HID, HID, 8, 6, 16, 16, 1, 0><<<gbG, 256>>>(
        pu, W2, pt2, pu, m1, s1, 0.25f, nullptr, nullptr);
    gather_kernel<HID, 1><<<gbW, 512>>>(pt2, pu, pt, m0, s0, psum + 2 * HID, psq + 2 * HID);
    bn_final_kernel<<<1, HID>>>(psum + 2 * HID, psq + 2 * HID, m2, s2);

    // ---- final: c = bn2relu(u) @ W3^T ; out = spmm(c) ----
    gemm_kernel<HID, OUTC, 4, 5, 8, 32, 1, 0><<<gbG, 256>>>(
        pu, W3, pc, nullptr, m2, s2, 1.f, nullptr, nullptr);
    gather_kernel<OUTC, 0><<<gbW, 512>>>(pc, out, nullptr, nullptr, nullptr, nullptr, nullptr);
}

// round 6
// speedup vs baseline: 2.2596x; 1.0860x over previous
#include <cuda_runtime.h>
#include <cuda_bf16.h>

#define NN 50000
#define NE 800000
#define INC 128
#define HID 96
#define OUTC 40
#define SCB 196   // scan blocks: 196*256 = 50176 >= NN

__device__ float g_dinv[NN];
__device__ float g_selfw[NN];
__device__ int   g_cnt[NN];
__device__ int   g_fill[NN];
__device__ int   g_rowptr[NN + 1];
__device__ int   g_bsum[256];
__device__ int   g_boff[256];
__device__ int   g_col[NE];
__device__ float g_ew[NE];
__device__ float g_t [NN * HID];   // layer-0 raw GEMM output (h0 source)
__device__ float g_t2[NN * HID];   // blended GEMM output per layer
__device__ float g_u [NN * HID];   // conv_resi output per layer
__device__ float g_c [NN * OUTC];
__device__ float g_sum[3 * HID];
__device__ float g_sq [3 * HID];
__device__ float g_meanL[3][HID];
__device__ float g_sclL [3][HID];

// ---------------------------------------------------------------------------
// helpers
// ---------------------------------------------------------------------------
typedef unsigned long long ull;

__device__ __forceinline__ void ffma2(ull& acc, ull a2, ull b2) {
    asm("fma.rn.f32x2 %0, %1, %2, %3;" : "=l"(acc) : "l"(a2), "l"(b2), "l"(acc));
}
__device__ __forceinline__ float2 unpack2(ull v) {
    float2 r;
    asm("mov.b64 {%0, %1}, %2;" : "=f"(r.x), "=f"(r.y) : "l"(v));
    return r;
}
__device__ __forceinline__ unsigned su32(const void* p) {
    return (unsigned)__cvta_generic_to_shared(p);
}
__device__ __forceinline__ ull lds64(unsigned a) {
    ull v;
    asm volatile("ld.shared.b64 %0, [%1];" : "=l"(v) : "r"(a));
    return v;
}

// ---------------------------------------------------------------------------
// Prep
// ---------------------------------------------------------------------------
__global__ void zero_prep_kernel() {
    int i = blockIdx.x * blockDim.x + threadIdx.x;
    if (i < NN) { g_cnt[i] = 0; g_fill[i] = 0; }
    if (i < 3 * HID) { g_sum[i] = 0.f; g_sq[i] = 0.f; }
}

__global__ void cnt_kernel(const int* __restrict__ ei) {
    int e = blockIdx.x * blockDim.x + threadIdx.x;
    if (e >= NE) return;
    int s = ei[e];
    int d = ei[NE + e];
    if (s != d) atomicAdd(&g_cnt[d], 1);
}

__global__ void scan1_kernel() {
    __shared__ int sh[256];
    int i = blockIdx.x * 256 + threadIdx.x;
    sh[threadIdx.x] = (i < NN) ? g_cnt[i] : 0;
    __syncthreads();
    for (int o = 128; o > 0; o >>= 1) {
        if (threadIdx.x < o) sh[threadIdx.x] += sh[threadIdx.x + o];
        __syncthreads();
    }
    if (threadIdx.x == 0) g_bsum[blockIdx.x] = sh[0];
}

__global__ void scan2_kernel() {
    __shared__ int sh[256];
    int t = threadIdx.x;
    int v = (t < SCB) ? g_bsum[t] : 0;
    sh[t] = v;
    __syncthreads();
    for (int o = 1; o < 256; o <<= 1) {
        int add = (t >= o) ? sh[t - o] : 0;
        __syncthreads();
        sh[t] += add;
        __syncthreads();
    }
    if (t < SCB) g_boff[t] = sh[t] - v;
    if (t == 255) g_rowptr[NN] = sh[255];
}

__global__ void scan3_kernel() {
    __shared__ int sh[256];
    int t = threadIdx.x;
    int i = blockIdx.x * 256 + t;
    int v = (i < NN) ? g_cnt[i] : 0;
    sh[t] = v;
    __syncthreads();
    for (int o = 1; o < 256; o <<= 1) {
        int add = (t >= o) ? sh[t - o] : 0;
        __syncthreads();
        sh[t] += add;
        __syncthreads();
    }
    if (i < NN) {
        g_rowptr[i] = g_boff[blockIdx.x] + sh[t] - v;
        float d = (float)v + 1.f;
        g_dinv[i]  = rsqrtf(d);
        g_selfw[i] = 1.f / d;
    }
}

__global__ void fill_kernel(const int* __restrict__ ei) {
    int e = blockIdx.x * blockDim.x + threadIdx.x;
    if (e >= NE) return;
    int s = ei[e];
    int d = ei[NE + e];
    if (s == d) return;
    int pos = g_rowptr[d] + atomicAdd(&g_fill[d], 1);
    g_col[pos] = s;
    g_ew[pos] = g_dinv[s] * g_dinv[d];
}

// ---------------------------------------------------------------------------
// SGEMM v2: W fully SMEM-resident (K-major, stride NOUT+2), A tile stored
// DUPLICATED (float2(v,v)) and double-buffered. Column-pair accumulators:
// acc2[r][c] = row (ty*TM+r), cols (tx*2*TNP + 2c, +1). Inner loop is pure
// LDS.64 + FFMA2 (no movs).
//   NORM=1: input a -> relu((a-mean)*scl) applied at staging
//   beta != 1: Out = beta*acc + (1-beta)*normA(blendSrc)
//   STATS=1: fused column sums/sumsq of Out
// Requires: TX*TY=256, TM*TY=128, TX*2*TNP=NOUT, K%16==0.
// ---------------------------------------------------------------------------
template <int K, int NOUT, int TM, int TNP, int TX, int TY, int NORM, int STATS>
__global__ void __launch_bounds__(256)
gemm_kernel(const float* __restrict__ A,
            const float* __restrict__ Wg,
            float* __restrict__ Out,
            const float* __restrict__ blendSrc,
            const float* __restrict__ mean,
            const float* __restrict__ scl,
            float beta,
            float* __restrict__ sums,
            float* __restrict__ sq) {
    constexpr int BM = TM * TY;         // 128
    constexpr int NT = TX * TY;         // 256
    constexpr int WSTR = NOUT + 2;      // keeps 8B align + shifted banks
    constexpr int NC = K / 16;
    constexpr int CN = 2 * TNP;         // cols per thread

    extern __shared__ char smem[];
    float*  ws   = (float*)smem;                                  // K*WSTR
    float2* xs   = (float2*)(smem + K * WSTR * 4);                // 2*16*BM
    float*  ssum = (float*)(smem + K * WSTR * 4 + 2 * 16 * BM * 8);
    float*  ssq  = ssum + NOUT;

    int tid = threadIdx.x;
    int tx = tid % TX;
    int ty = tid / TX;
    int rowbase = blockIdx.x * BM;

    if (STATS) {
        for (int i = tid; i < NOUT; i += NT) { ssum[i] = 0.f; ssq[i] = 0.f; }
    }

    // ---- load W transposed into SMEM (once) ----
    constexpr int K4 = K / 4;
    for (int i = tid; i < NOUT * K4; i += NT) {
        int n = i / K4, q = i % K4;
        float4 w = __ldg((const float4*)&Wg[(size_t)n * K + q * 4]);
        ws[(q * 4 + 0) * WSTR + n] = w.x;
        ws[(q * 4 + 1) * WSTR + n] = w.y;
        ws[(q * 4 + 2) * WSTR + n] = w.z;
        ws[(q * 4 + 3) * WSTR + n] = w.w;
    }

    // ---- A chunk staging helpers ----
    auto ldA = [&](int ch, int i) -> float4 {
        int r = i >> 2, c4 = (i & 3) * 4;
        int row = rowbase + r;
        int k = ch * 16 + c4;
        float4 v = (row < NN) ? __ldg((const float4*)&A[(size_t)row * K + k])
                              : make_float4(0.f, 0.f, 0.f, 0.f);
        if (NORM) {
            float4 m = __ldg((const float4*)&mean[k]);
            float4 s = __ldg((const float4*)&scl[k]);
            v.x = fmaxf((v.x - m.x) * s.x, 0.f);
            v.y = fmaxf((v.y - m.y) * s.y, 0.f);
            v.z = fmaxf((v.z - m.z) * s.z, 0.f);
            v.w = fmaxf((v.w - m.w) * s.w, 0.f);
        }
        return v;
    };
    auto stA = [&](int buf, int i, float4 v) {
        int r = i >> 2, c4 = (i & 3) * 4;
        float2* base = &xs[(size_t)(buf * 16) * BM + r];
        base[(c4 + 0) * BM] = make_float2(v.x, v.x);
        base[(c4 + 1) * BM] = make_float2(v.y, v.y);
        base[(c4 + 2) * BM] = make_float2(v.z, v.z);
        base[(c4 + 3) * BM] = make_float2(v.w, v.w);
    };

    // prologue: stage chunk 0
    stA(0, tid, ldA(0, tid));
    stA(0, tid + 256, ldA(0, tid + 256));
    __syncthreads();

    ull acc2[TM][TNP];
#pragma unroll
    for (int r = 0; r < TM; r++)
#pragma unroll
        for (int c = 0; c < TNP; c++) acc2[r][c] = 0ull;

    unsigned xsb = su32(xs);
    unsigned wsb = su32(ws);
    unsigned athr = xsb + (unsigned)(ty * TM) * 8u;
    unsigned bthr = wsb + (unsigned)(tx * CN) * 4u;

#pragma unroll 2
    for (int ch = 0; ch < NC; ch++) {
        bool pre = (ch + 1 < NC);
        float4 p0, p1;
        if (pre) { p0 = ldA(ch + 1, tid); p1 = ldA(ch + 1, tid + 256); }

        unsigned abase = athr + (unsigned)((ch & 1) * 16 * BM) * 8u;
        unsigned bbase = bthr + (unsigned)(ch * 16 * WSTR) * 4u;
#pragma unroll
        for (int kk = 0; kk < 16; kk++) {
            ull a2[TM], b2[TNP];
#pragma unroll
            for (int r = 0; r < TM; r++)
                a2[r] = lds64(abase + (unsigned)(kk * BM + r) * 8u);
#pragma unroll
            for (int c = 0; c < TNP; c++)
                b2[c] = lds64(bbase + (unsigned)(kk * WSTR) * 4u + (unsigned)c * 8u);
#pragma unroll
            for (int r = 0; r < TM; r++)
#pragma unroll
                for (int c = 0; c < TNP; c++) ffma2(acc2[r][c], a2[r], b2[c]);
        }

        if (pre) {
            int buf = (ch + 1) & 1;
            stA(buf, tid, p0);
            stA(buf, tid + 256, p1);
        }
        __syncthreads();
    }

    // ---- epilogue ----
    float colsum[CN], colsq[CN];
    if (STATS) {
#pragma unroll
        for (int c = 0; c < CN; c++) { colsum[c] = 0.f; colsq[c] = 0.f; }
    }

#pragma unroll
    for (int r = 0; r < TM; r++) {
        int row = rowbase + ty * TM + r;
        if (row >= NN) continue;
#pragma unroll
        for (int c = 0; c < TNP; c++) {
            int col = tx * CN + 2 * c;
            float2 v = unpack2(acc2[r][c]);
            if (beta != 1.f) {
                float2 b = *(const float2*)&blendSrc[(size_t)row * NOUT + col];
                if (NORM) {
                    b.x = fmaxf((b.x - mean[col + 0]) * scl[col + 0], 0.f);
                    b.y = fmaxf((b.y - mean[col + 1]) * scl[col + 1], 0.f);
                }
                v.x = beta * v.x + (1.f - beta) * b.x;
                v.y = beta * v.y + (1.f - beta) * b.y;
            }
            *(float2*)&Out[(size_t)row * NOUT + col] = v;
            if (STATS) {
                colsum[2 * c] += v.x;     colsq[2 * c] += v.x * v.x;
                colsum[2 * c + 1] += v.y; colsq[2 * c + 1] += v.y * v.y;
            }
        }
    }

    if (STATS) {
#pragma unroll
        for (int c = 0; c < CN; c++) {
            atomicAdd(&ssum[tx * CN + c], colsum[c]);
            atomicAdd(&ssq[tx * CN + c], colsq[c]);
        }
        __syncthreads();
        for (int i = tid; i < NOUT; i += NT) {
            atomicAdd(&sums[i], ssum[i]);
            atomicAdd(&sq[i], ssq[i]);
        }
    }
}

// ---------------------------------------------------------------------------
// BN finalize
// ---------------------------------------------------------------------------
__global__ void bn_final_kernel(const float* __restrict__ sums,
                                const float* __restrict__ sq,
                                float* __restrict__ mean,
                                float* __restrict__ scl) {
    int c = threadIdx.x;
    if (c < HID) {
        const float invN = 1.f / (float)NN;
        float m = sums[c] * invN;
        float v = sq[c] * invN - m * m;
        mean[c] = m;
        scl[c] = rsqrtf(v + 1e-5f);
    }
}

// ---------------------------------------------------------------------------
// CSR gather SpMM, warp per node, float4 lanes, edge loop unrolled x4.
// MODE 1: Y = 0.9*(sum + selfw*X) + 0.1*relu(bn0(h0raw)), fused col stats of Y
// MODE 0: Y = sum + selfw*X
// Grid covers exactly NN warps.
// ---------------------------------------------------------------------------
template <int F, int MODE>
__global__ void gather_kernel(const float* __restrict__ X, float* __restrict__ Y,
                              const float* __restrict__ h0raw,
                              const float* __restrict__ mean0,
                              const float* __restrict__ scl0,
                              float* __restrict__ sums,
                              float* __restrict__ sq) {
    constexpr int NV = F / 4;
    __shared__ float ssum[HID];
    __shared__ float ssq[HID];
    int tid = threadIdx.x;
    if (MODE == 1) {
        if (tid < F) { ssum[tid] = 0.f; ssq[tid] = 0.f; }
        __syncthreads();
    }
    int node = blockIdx.x * (blockDim.x >> 5) + (tid >> 5);
    int lane = tid & 31;
    bool act = lane < NV;
    const float4* Xv = (const float4*)X;

    float4 sum = make_float4(0.f, 0.f, 0.f, 0.f);
    int p   = g_rowptr[node];
    int end = g_rowptr[node + 1];

    for (; p + 4 <= end; p += 4) {
        int   c0 = __ldg(&g_col[p]),     c1 = __ldg(&g_col[p + 1]);
        int   c2 = __ldg(&g_col[p + 2]), c3 = __ldg(&g_col[p + 3]);
        float w0 = __ldg(&g_ew[p]),      w1 = __ldg(&g_ew[p + 1]);
        float w2 = __ldg(&g_ew[p + 2]),  w3 = __ldg(&g_ew[p + 3]);
        if (act) {
            float4 v0 = __ldg(&Xv[(size_t)c0 * NV + lane]);
            float4 v1 = __ldg(&Xv[(size_t)c1 * NV + lane]);
            float4 v2 = __ldg(&Xv[(size_t)c2 * NV + lane]);
            float4 v3 = __ldg(&Xv[(size_t)c3 * NV + lane]);
            sum.x += w0 * v0.x + w1 * v1.x + w2 * v2.x + w3 * v3.x;
            sum.y += w0 * v0.y + w1 * v1.y + w2 * v2.y + w3 * v3.y;
            sum.z += w0 * v0.z + w1 * v1.z + w2 * v2.z + w3 * v3.z;
            sum.w += w0 * v0.w + w1 * v1.w + w2 * v2.w + w3 * v3.w;
        }
    }
    for (; p < end; p++) {
        int c = __ldg(&g_col[p]);
        float w = __ldg(&g_ew[p]);
        if (act) {
            float4 v = __ldg(&Xv[(size_t)c * NV + lane]);
            sum.x += w * v.x; sum.y += w * v.y;
            sum.z += w * v.z; sum.w += w * v.w;
        }
    }

    if (act) {
        float sw = g_selfw[node];
        float4 xv = __ldg(&Xv[(size_t)node * NV + lane]);
        float4 v;
        v.x = sum.x + sw * xv.x;
        v.y = sum.y + sw * xv.y;
        v.z = sum.z + sw * xv.z;
        v.w = sum.w + sw * xv.w;
        if (MODE == 1) {
            float4 m  = __ldg(&((const float4*)mean0)[lane]);
            float4 s  = __ldg(&((const float4*)scl0)[lane]);
            float4 hr = __ldg(&((const float4*)h0raw)[(size_t)node * NV + lane]);
            v.x = 0.9f * v.x + 0.1f * fmaxf((hr.x - m.x) * s.x, 0.f);
            v.y = 0.9f * v.y + 0.1f * fmaxf((hr.y - m.y) * s.y, 0.f);
            v.z = 0.9f * v.z + 0.1f * fmaxf((hr.z - m.z) * s.z, 0.f);
            v.w = 0.9f * v.w + 0.1f * fmaxf((hr.w - m.w) * s.w, 0.f);
        }
        ((float4*)Y)[(size_t)node * NV + lane] = v;
        if (MODE == 1) {
            int col = lane * 4;
            atomicAdd(&ssum[col + 0], v.x);
            atomicAdd(&ssum[col + 1], v.y);
            atomicAdd(&ssum[col + 2], v.z);
            atomicAdd(&ssum[col + 3], v.w);
            atomicAdd(&ssq[col + 0], v.x * v.x);
            atomicAdd(&ssq[col + 1], v.y * v.y);
            atomicAdd(&ssq[col + 2], v.z * v.z);
            atomicAdd(&ssq[col + 3], v.w * v.w);
        }
    }

    if (MODE == 1) {
        __syncthreads();
        if (tid < F) {
            atomicAdd(&sums[tid], ssum[tid]);
            atomicAdd(&sq[tid], ssq[tid]);
        }
    }
}

// ---------------------------------------------------------------------------
extern "C" void kernel_launch(void* const* d_in, const int* in_sizes, int n_in,
                              void* d_out, int out_size) {
    const float* x  = (const float*)d_in[0];
    const int*   ei = (const int*)d_in[1];
    const float* W0 = (const float*)d_in[2];
    const float* W1 = (const float*)d_in[3];
    const float* W2 = (const float*)d_in[4];
    const float* W3 = (const float*)d_in[5];
    float* out = (float*)d_out;

    float *pt, *pt2, *pu, *pc, *psum, *psq, *pmean, *pscl;
    cudaGetSymbolAddress((void**)&pt, g_t);
    cudaGetSymbolAddress((void**)&pt2, g_t2);
    cudaGetSymbolAddress((void**)&pu, g_u);
    cudaGetSymbolAddress((void**)&pc, g_c);
    cudaGetSymbolAddress((void**)&psum, g_sum);
    cudaGetSymbolAddress((void**)&psq, g_sq);
    cudaGetSymbolAddress((void**)&pmean, g_meanL);
    cudaGetSymbolAddress((void**)&pscl, g_sclL);

    const int gbE = (NE + 255) / 256;
    const int gbN = (NN + 255) / 256;
    const int gbG = (NN + 127) / 128;
    const int gbW = NN / 16;

    float* m0 = pmean + 0 * HID; float* s0 = pscl + 0 * HID;
    float* m1 = pmean + 1 * HID; float* s1 = pscl + 1 * HID;
    float* m2 = pmean + 2 * HID; float* s2 = pscl + 2 * HID;

    // dynamic smem sizes: ws + dup A double buffer + stats
    const int xsBytes = 2 * 16 * 128 * 8;  // 32768
    const int sm0 = 128 * 98 * 4 + xsBytes + 96 * 8 + 64;
    const int sm1 = 96 * 98 * 4 + xsBytes + 96 * 8 + 64;
    const int sm3 = 96 * 42 * 4 + xsBytes + 40 * 8 + 64;

    auto k0 = gemm_kernel<INC, HID, 8, 3, 16, 16, 0, 1>;
    auto k12 = gemm_kernel<HID, HID, 8, 3, 16, 16, 1, 0>;
    auto k3 = gemm_kernel<HID, OUTC, 2, 5, 4, 64, 1, 0>;
    cudaFuncSetAttribute(k0, cudaFuncAttributeMaxDynamicSharedMemorySize, sm0);
    cudaFuncSetAttribute(k12, cudaFuncAttributeMaxDynamicSharedMemorySize, sm1);
    cudaFuncSetAttribute(k3, cudaFuncAttributeMaxDynamicSharedMemorySize, sm3);

    // ---- prep + layer-0 GEMM (slot 4 for the ncu capture window) ----
    zero_prep_kernel<<<gbN, 256>>>();
    cnt_kernel<<<gbE, 256>>>(ei);
    scan1_kernel<<<SCB, 256>>>();
    k0<<<gbG, 256, sm0>>>(x, W0, pt, nullptr, nullptr, nullptr, 1.f,
                          psum + 0 * HID, psq + 0 * HID);
    scan2_kernel<<<1, 256>>>();
    scan3_kernel<<<SCB, 256>>>();
    fill_kernel<<<gbE, 256>>>(ei);
    bn_final_kernel<<<1, HID>>>(psum + 0 * HID, psq + 0 * HID, m0, s0);

    // ---- layer 1 (beta = 0.5) ----
    k12<<<gbG, 256, sm1>>>(pt, W1, pt2, pt, m0, s0, 0.5f, nullptr, nullptr);
    gather_kernel<HID, 1><<<gbW, 512>>>(pt2, pu, pt, m0, s0, psum + 1 * HID, psq + 1 * HID);
    bn_final_kernel<<<1, HID>>>(psum + 1 * HID, psq + 1 * HID, m1, s1);

    // ---- layer 2 (beta = 0.25) ----
    k12<<<gbG, 256, sm1>>>(pu, W2, pt2, pu, m1, s1, 0.25f, nullptr, nullptr);
    gather_kernel<HID, 1><<<gbW, 512>>>(pt2, pu, pt, m0, s0, psum + 2 * HID, psq + 2 * HID);
    bn_final_kernel<<<1, HID>>>(psum + 2 * HID, psq + 2 * HID, m2, s2);

    // ---- final: c = bn2relu(u) @ W3^T ; out = spmm(c) ----
    k3<<<gbG, 256, sm3>>>(pu, W3, pc, nullptr, m2, s2, 1.f, nullptr, nullptr);
    gather_kernel<OUTC, 0><<<gbW, 512>>>(pc, out, nullptr, nullptr, nullptr, nullptr, nullptr);
}